// round 1
// baseline (speedup 1.0000x reference)
#include <cuda_runtime.h>

#define NTRAJ 2048
#define TSTEPS 512

// Transposed measurements: [t][k][traj] for coalesced mainloop loads. 12 MB.
__device__ float g_zt[TSTEPS * 3 * NTRAJ];

__global__ void transpose_k(const float* __restrict__ meas, int n) {
    int i = blockIdx.x * blockDim.x + threadIdx.x;
    if (i < n) {
        int traj = i / (TSTEPS * 3);
        int rem  = i - traj * (TSTEPS * 3);   // = t*3 + k
        g_zt[rem * NTRAJ + traj] = meas[i];
    }
}

__device__ __forceinline__ float ftanh(float u) {
    float au = fabsf(u);
    float e  = __expf(au + au);
    float t  = 1.0f - __fdividef(2.0f, e + 1.0f);
    return (u < 0.0f) ? -t : t;
}

__global__ void __launch_bounds__(32) ekf_k(
    const float* __restrict__ init_state,
    const float* __restrict__ dyna,
    const float* __restrict__ Q,
    const float* __restrict__ R,
    const float* __restrict__ P0,
    float* __restrict__ out)
{
    const int traj = blockIdx.x * 32 + threadIdx.x;
    const float dt = 1.0f / 120.0f;

    const float fric = __ldg(dyna + 0);
    const float damp = __ldg(dyna + 1);

    // Per-block process/measurement noise (diagonal entries of Q, R)
    const float qx0 = __ldg(Q + 0),  qx1 = __ldg(Q + 14);   // (0,0),(2,2)
    const float qy0 = __ldg(Q + 7),  qy1 = __ldg(Q + 21);   // (1,1),(3,3)
    const float qt0 = __ldg(Q + 28), qt1 = __ldg(Q + 35);   // (4,4),(5,5)
    const float rx  = __ldg(R + 0),  ry  = __ldg(R + 4), rth = __ldg(R + 8);

    // State
    float x   = init_state[traj * 6 + 0];
    float y_  = init_state[traj * 6 + 1];
    float dx  = init_state[traj * 6 + 2];
    float dy  = init_state[traj * 6 + 3];
    float th  = init_state[traj * 6 + 4];
    float dth = init_state[traj * 6 + 5];

    // Covariance blocks (p00, p01, p11) for {x,dx}, {y,dy}, {th,dth}
    float pxa = __ldg(P0 + 0),  pxb = __ldg(P0 + 2),  pxc = __ldg(P0 + 14);
    float pya = __ldg(P0 + 7),  pyb = __ldg(P0 + 9),  pyc = __ldg(P0 + 21);
    float pta = __ldg(P0 + 28), ptb = __ldg(P0 + 29), ptc = __ldg(P0 + 35);

    const float* z = g_zt + traj;
    float zx = z[0], zy = z[NTRAJ], zth = z[2 * NTRAJ];
    float* o = out + traj * TSTEPS;

    #pragma unroll 1
    for (int t = 0; t < TSTEPS; ++t) {
        // --- prefetch next measurement (coalesced; hits L2) ---
        int tn = (t + 1 < TSTEPS) ? (t + 1) : t;
        float nzx  = z[(3 * tn + 0) * NTRAJ];
        float nzy  = z[(3 * tn + 1) * NTRAJ];
        float nzth = z[(3 * tn + 2) * NTRAJ];

        // ================= x block =================
        float xp  = x + dt * dx;
        float tx  = ftanh(100.0f * dx);
        float dxp = dx - dt * (damp * dx + fric * tx);
        float ax  = 1.0f - dt * (damp + fric * (100.0f - 100.0f * tx * tx));
        float ux  = pxb + dt * pxc;
        float p00x = (pxa + dt * pxb) + dt * ux + qx0;
        float p01x = ax * ux;
        float p11x = ax * (ax * pxc) + qx1;
        float Sx = p00x + rx;
        float ix = __frcp_rn(Sx);
        float yx = zx - xp;
        float K0x = __fmul_rn(p00x, ix);
        float K1x = __fmul_rn(p01x, ix);
        x  = xp  + K0x * yx;
        dx = dxp + K1x * yx;
        float ox = 1.0f - K0x;
        pxa = ox * p00x; pxb = ox * p01x; pxc = p11x - K1x * p01x;

        // ================= y block =================
        float yp  = y_ + dt * dy;
        float ty  = ftanh(100.0f * dy);
        float dyp = dy - dt * (damp * dy + fric * ty);
        float ay  = 1.0f - dt * (damp + fric * (100.0f - 100.0f * ty * ty));
        float uy  = pyb + dt * pyc;
        float p00y = (pya + dt * pyb) + dt * uy + qy0;
        float p01y = ay * uy;
        float p11y = ay * (ay * pyc) + qy1;
        float Sy = p00y + ry;
        float iy = __frcp_rn(Sy);
        float yy = zy - yp;
        float K0y = __fmul_rn(p00y, iy);
        float K1y = __fmul_rn(p01y, iy);
        y_ = yp  + K0y * yy;
        dy = dyp + K1y * yy;
        float oy = 1.0f - K0y;
        pya = oy * p00y; pyb = oy * p01y; pyc = p11y - K1y * p01y;

        // ================= theta block (linear, a = 1) =================
        float thp = th + dt * dth;
        float ut  = ptb + dt * ptc;
        float p00t = (pta + dt * ptb) + dt * ut + qt0;
        float p01t = ut;
        float p11t = ptc + qt1;
        float St = p00t + rth;
        float it = __frcp_rn(St);
        float yt = zth - thp;
        float K0t = __fmul_rn(p00t, it);
        float K1t = __fmul_rn(p01t, it);
        th  = thp + K0t * yt;
        dth = dth + K1t * yt;
        float ot = 1.0f - K0t;
        pta = ot * p00t; ptb = ot * p01t; ptc = p11t - K1t * p01t;

        // ================= loss =================
        float det = (Sx * Sy) * St;
        float mah = yx * (ix * yx) + yy * (iy * yy) + yt * (it * yt);
        o[t] = det + mah;

        zx = nzx; zy = nzy; zth = nzth;
    }
}

extern "C" void kernel_launch(void* const* d_in, const int* in_sizes, int n_in,
                              void* d_out, int out_size) {
    const float* meas = (const float*)d_in[0];
    const float* init = (const float*)d_in[1];
    const float* dyna = (const float*)d_in[2];
    const float* Q    = (const float*)d_in[3];
    const float* R    = (const float*)d_in[4];
    const float* P0   = (const float*)d_in[5];
    float* out = (float*)d_out;

    int n = NTRAJ * TSTEPS * 3;
    transpose_k<<<(n + 255) / 256, 256>>>(meas, n);
    ekf_k<<<NTRAJ / 32, 32>>>(init, dyna, Q, R, P0, out);
}

// round 2
// speedup vs baseline: 1.5840x; 1.5840x over previous
#include <cuda_runtime.h>

#define NTRAJ 2048
#define TSTEPS 512

// Transposed measurements: [t][k][traj] for coalesced mainloop loads. 12 MB.
__device__ float g_zt[TSTEPS * 3 * NTRAJ];

__global__ void transpose_k(const float* __restrict__ meas, int n) {
    int i = blockIdx.x * blockDim.x + threadIdx.x;
    if (i < n) {
        int traj = i / (TSTEPS * 3);
        int rem  = i - traj * (TSTEPS * 3);   // = t*3 + k
        g_zt[rem * NTRAJ + traj] = meas[i];
    }
}

__device__ __forceinline__ float ftanh(float u) {
    float au = fabsf(u);
    float e  = __expf(au + au);
    float t  = 1.0f - __fdividef(2.0f, e + 1.0f);
    return (u < 0.0f) ? -t : t;
}

// One warp handles 8 trajectories; lanes (c = lane>>3, j = lane&7) run the
// c-th independent 2x2 Kalman block of trajectory (warp*8 + j).
// Theta block is made uniform by zeroing fric/damp per-lane (exact math).
// Loss combined across the 3 component lanes via shuffles, no barriers.
__global__ void __launch_bounds__(32) ekf_k(
    const float* __restrict__ init_state,
    const float* __restrict__ dyna,
    const float* __restrict__ Q,
    const float* __restrict__ R,
    const float* __restrict__ P0,
    float* __restrict__ out)
{
    const int lane = threadIdx.x & 31;
    int c = lane >> 3; if (c > 2) c = 2;       // lanes 24-31 duplicate c=2 (unused)
    const int j    = lane & 7;
    const int traj = blockIdx.x * 8 + j;

    const float dt = 1.0f / 120.0f;

    const bool lin = (c == 2);
    const float fric = lin ? 0.0f : __ldg(dyna + 0);
    const float damp = lin ? 0.0f : __ldg(dyna + 1);

    // component -> state indices: pos {0,1,4}, vel {2,3,5}
    const int pc = lin ? 4 : c;
    const int vc = lin ? 5 : c + 2;

    const float q0 = __ldg(Q + pc * 7);
    const float q1 = __ldg(Q + vc * 7);
    const float r  = __ldg(R + c * 4);

    float s0 = init_state[traj * 6 + pc];      // position-like
    float s1 = init_state[traj * 6 + vc];      // velocity-like

    float p00 = __ldg(P0 + pc * 7);
    float p01 = __ldg(P0 + pc * 6 + vc);
    float p11 = __ldg(P0 + vc * 7);

    const float* zb = g_zt + c * NTRAJ + traj;
    float z = zb[0];
    float* o = out + traj * TSTEPS;

    float lb0, lb1, lb2;

    #pragma unroll 4
    for (int t = 0; t < TSTEPS; ++t) {
        // prefetch next measurement (coalesced within c-group; L2 resident)
        int tn = (t + 1 < TSTEPS) ? (t + 1) : t;
        float zn = zb[3 * tn * NTRAJ];

        // ---- predict (dynamics + Jacobian diag-block) ----
        float sp  = s0 + dt * s1;
        float tv  = ftanh(100.0f * s1);
        float vp  = s1 - dt * (damp * s1 + fric * tv);
        float a   = 1.0f - dt * (damp + fric * (100.0f - 100.0f * tv * tv));

        float u    = p01 + dt * p11;
        float n00  = (p00 + dt * p01) + dt * u + q0;
        float n01  = a * u;
        float n11  = a * (a * p11) + q1;

        // ---- update (scalar observation) ----
        float S  = n00 + r;
        float is = __frcp_rn(S);
        float yv = z - sp;
        float K0 = __fmul_rn(n00, is);
        float K1 = __fmul_rn(n01, is);
        s0 = sp + K0 * yv;
        s1 = vp + K1 * yv;
        float om = 1.0f - K0;
        p00 = om * n00;
        p01 = om * n01;
        p11 = n11 - K1 * n01;

        float mah = yv * (is * yv);

        // ---- combine across component lanes (c=0 lanes get valid result) ----
        float S8  = __shfl_down_sync(0xFFFFFFFFu, S, 8);
        float S16 = __shfl_down_sync(0xFFFFFFFFu, S, 16);
        float m8  = __shfl_down_sync(0xFFFFFFFFu, mah, 8);
        float m16 = __shfl_down_sync(0xFFFFFFFFu, mah, 16);
        float loss = (S * S8) * S16 + (mah + m8 + m16);

        int ph = t & 3;
        if (ph == 0) lb0 = loss;
        else if (ph == 1) lb1 = loss;
        else if (ph == 2) lb2 = loss;
        else if (lane < 8) {
            float4 v = make_float4(lb0, lb1, lb2, loss);
            *reinterpret_cast<float4*>(o + (t - 3)) = v;
        }

        z = zn;
    }
}

extern "C" void kernel_launch(void* const* d_in, const int* in_sizes, int n_in,
                              void* d_out, int out_size) {
    const float* meas = (const float*)d_in[0];
    const float* init = (const float*)d_in[1];
    const float* dyna = (const float*)d_in[2];
    const float* Q    = (const float*)d_in[3];
    const float* R    = (const float*)d_in[4];
    const float* P0   = (const float*)d_in[5];
    float* out = (float*)d_out;

    int n = NTRAJ * TSTEPS * 3;
    transpose_k<<<(n + 255) / 256, 256>>>(meas, n);
    ekf_k<<<NTRAJ / 8, 32>>>(init, dyna, Q, R, P0, out);
}

// round 3
// speedup vs baseline: 3.0042x; 1.8966x over previous
#include <cuda_runtime.h>

#define NTRAJ 2048
#define TSTEPS 512
#define KDIM   (TSTEPS * 3)   // 1536 floats per trajectory
#define PF 8                  // prefetch depth (measurement loads in flight)

// Transposed measurements: [t*3+k][traj] for coalesced mainloop loads. 12 MB.
__device__ float g_zt[KDIM * NTRAJ];

// Tiled transpose: meas[traj][rem] -> g_zt[rem][traj], both sides coalesced.
__global__ void transpose_k(const float* __restrict__ meas) {
    __shared__ float tile[32][33];
    int rem0  = blockIdx.x * 32;
    int traj0 = blockIdx.y * 32;
    int r  = rem0 + threadIdx.x;
    int tj = traj0 + threadIdx.y;
    tile[threadIdx.y][threadIdx.x] = meas[tj * KDIM + r];
    __syncthreads();
    r  = rem0 + threadIdx.y;
    tj = traj0 + threadIdx.x;
    g_zt[r * NTRAJ + tj] = tile[threadIdx.x][threadIdx.y];
}

__device__ __forceinline__ float ftanh(float u) {
    float au = fabsf(u);
    float e  = __expf(au + au);
    float t  = 1.0f - __fdividef(2.0f, e + 1.0f);
    return (u < 0.0f) ? -t : t;
}

// One warp handles 8 trajectories; lanes (c = lane>>3, j = lane&7) run the
// c-th independent 2x2 Kalman block of trajectory (warp*8 + j).
// Theta block made uniform by zeroing fric/damp per-lane (exact math).
// Measurements prefetched PF steps ahead through a register ring buffer.
__global__ void __launch_bounds__(32) ekf_k(
    const float* __restrict__ init_state,
    const float* __restrict__ dyna,
    const float* __restrict__ Q,
    const float* __restrict__ R,
    const float* __restrict__ P0,
    float* __restrict__ out)
{
    const int lane = threadIdx.x & 31;
    int c = lane >> 3; if (c > 2) c = 2;       // lanes 24-31 duplicate c=2 (unused)
    const int j    = lane & 7;
    const int traj = blockIdx.x * 8 + j;

    const float dt = 1.0f / 120.0f;

    const bool lin = (c == 2);
    const float fric = lin ? 0.0f : __ldg(dyna + 0);
    const float damp = lin ? 0.0f : __ldg(dyna + 1);

    // component -> state indices: pos {0,1,4}, vel {2,3,5}
    const int pc = lin ? 4 : c;
    const int vc = lin ? 5 : c + 2;

    const float q0 = __ldg(Q + pc * 7);
    const float q1 = __ldg(Q + vc * 7);
    const float r  = __ldg(R + c * 4);

    float s0 = init_state[traj * 6 + pc];      // position-like
    float s1 = init_state[traj * 6 + vc];      // velocity-like

    float p00 = __ldg(P0 + pc * 7);
    float p01 = __ldg(P0 + pc * 6 + vc);
    float p11 = __ldg(P0 + vc * 7);

    const float* zb = g_zt + c * NTRAJ + traj; // element (t,c,traj) at zb[3*t*NTRAJ]
    float* o = out + traj * TSTEPS;

    // ---- prime the prefetch ring ----
    float zr[PF];
    #pragma unroll
    for (int i = 0; i < PF; ++i) zr[i] = zb[3 * i * NTRAJ];

    const float* pz = zb + 3 * PF * NTRAJ;     // next address to prefetch

    float lb0, lb1, lb2;

    #pragma unroll 1
    for (int t = 0; t < TSTEPS; t += PF) {
        #pragma unroll
        for (int u8 = 0; u8 < PF; ++u8) {
            const int t_ = t + u8;
            float z = zr[u8];

            // issue prefetch PF steps ahead (predicated off near the tail)
            float znew = 0.0f;
            if (t_ + PF < TSTEPS) znew = pz[3 * u8 * NTRAJ];
            zr[u8] = znew;

            // ---- predict (dynamics + Jacobian diag-block) ----
            float sp  = s0 + dt * s1;
            float tv  = ftanh(100.0f * s1);
            float vp  = s1 - dt * (damp * s1 + fric * tv);
            float a   = 1.0f - dt * (damp + fric * (100.0f - 100.0f * tv * tv));

            float u    = p01 + dt * p11;
            float n00  = (p00 + dt * p01) + dt * u + q0;
            float n01  = a * u;
            float n11  = a * (a * p11) + q1;

            // ---- update (scalar observation) ----
            float S  = n00 + r;
            float is = __frcp_rn(S);
            float yv = z - sp;
            float K0 = __fmul_rn(n00, is);
            float K1 = __fmul_rn(n01, is);
            s0 = sp + K0 * yv;
            s1 = vp + K1 * yv;
            float om = 1.0f - K0;
            p00 = om * n00;
            p01 = om * n01;
            p11 = n11 - K1 * n01;

            float mah = yv * (is * yv);

            // ---- combine across component lanes (c=0 lanes valid) ----
            float S8  = __shfl_down_sync(0xFFFFFFFFu, S, 8);
            float S16 = __shfl_down_sync(0xFFFFFFFFu, S, 16);
            float m8  = __shfl_down_sync(0xFFFFFFFFu, mah, 8);
            float m16 = __shfl_down_sync(0xFFFFFFFFu, mah, 16);
            float loss = (S * S8) * S16 + (mah + m8 + m16);

            const int ph = u8 & 3;
            if (ph == 0) lb0 = loss;
            else if (ph == 1) lb1 = loss;
            else if (ph == 2) lb2 = loss;
            else if (lane < 8) {
                float4 v = make_float4(lb0, lb1, lb2, loss);
                *reinterpret_cast<float4*>(o + (t_ - 3)) = v;
            }
        }
        pz += 3 * PF * NTRAJ;
    }
}

extern "C" void kernel_launch(void* const* d_in, const int* in_sizes, int n_in,
                              void* d_out, int out_size) {
    const float* meas = (const float*)d_in[0];
    const float* init = (const float*)d_in[1];
    const float* dyna = (const float*)d_in[2];
    const float* Q    = (const float*)d_in[3];
    const float* R    = (const float*)d_in[4];
    const float* P0   = (const float*)d_in[5];
    float* out = (float*)d_out;

    dim3 tgrid(KDIM / 32, NTRAJ / 32);
    dim3 tblk(32, 32);
    transpose_k<<<tgrid, tblk>>>(meas);
    ekf_k<<<NTRAJ / 8, 32>>>(init, dyna, Q, R, P0, out);
}

// round 4
// speedup vs baseline: 3.5815x; 1.1922x over previous
#include <cuda_runtime.h>

#define NTRAJ 2048
#define TSTEPS 512
#define KDIM   (TSTEPS * 3)   // 1536 floats per trajectory
#define PF 8                  // prefetch depth (measurement loads in flight)

// Transposed measurements: [t*3+k][traj] for coalesced mainloop loads. 12 MB.
__device__ float g_zt[KDIM * NTRAJ];

// Tiled transpose: meas[traj][rem] -> g_zt[rem][traj], both sides coalesced.
__global__ void transpose_k(const float* __restrict__ meas) {
    __shared__ float tile[32][33];
    int rem0  = blockIdx.x * 32;
    int traj0 = blockIdx.y * 32;
    int r  = rem0 + threadIdx.x;
    int tj = traj0 + threadIdx.y;
    tile[threadIdx.y][threadIdx.x] = meas[tj * KDIM + r];
    __syncthreads();
    r  = rem0 + threadIdx.y;
    tj = traj0 + threadIdx.x;
    g_zt[r * NTRAJ + tj] = tile[threadIdx.x][threadIdx.y];
}

// Hardware tanh (sm_75+): single MUFU op, ~16 cyc vs ~60 for the exp/rcp chain.
__device__ __forceinline__ float htanh(float x) {
    float y;
    asm("tanh.approx.f32 %0, %1;" : "=f"(y) : "f"(x));
    return y;
}

// One warp handles 8 trajectories; lanes (c = lane>>3, j = lane&7) run the
// c-th independent 2x2 Kalman block of trajectory (warp*8 + j).
// Theta block made uniform by zeroing fric/damp per-lane (exact math).
// Measurements prefetched PF steps ahead through a register ring buffer.
__global__ void __launch_bounds__(32) ekf_k(
    const float* __restrict__ init_state,
    const float* __restrict__ dyna,
    const float* __restrict__ Q,
    const float* __restrict__ R,
    const float* __restrict__ P0,
    float* __restrict__ out)
{
    const int lane = threadIdx.x & 31;
    int c = lane >> 3; if (c > 2) c = 2;       // lanes 24-31 duplicate c=2 (unused)
    const int j    = lane & 7;
    const int traj = blockIdx.x * 8 + j;

    const float dt = 1.0f / 120.0f;

    const bool lin = (c == 2);
    const float fric = lin ? 0.0f : __ldg(dyna + 0);
    const float damp = lin ? 0.0f : __ldg(dyna + 1);

    // hoisted per-lane dynamics constants
    const float c1 = 1.0f - dt * damp;     // velocity decay
    const float c2 = dt * fric;            // Coulomb magnitude
    const float c3 = 100.0f * c2;          // Jacobian tanh' scale
    const float c4 = c1 - c3;              // a = c4 + c3*tv^2

    // component -> state indices: pos {0,1,4}, vel {2,3,5}
    const int pc = lin ? 4 : c;
    const int vc = lin ? 5 : c + 2;

    const float q0 = __ldg(Q + pc * 7);
    const float q1 = __ldg(Q + vc * 7);
    const float r  = __ldg(R + c * 4);

    float s0 = init_state[traj * 6 + pc];      // position-like
    float s1 = init_state[traj * 6 + vc];      // velocity-like

    float p00 = __ldg(P0 + pc * 7);
    float p01 = __ldg(P0 + pc * 6 + vc);
    float p11 = __ldg(P0 + vc * 7);

    const float* zb = g_zt + c * NTRAJ + traj; // element (t,c,traj) at zb[3*t*NTRAJ]
    float* o = out + traj * TSTEPS;

    // ---- prime the prefetch ring ----
    float zr[PF];
    #pragma unroll
    for (int i = 0; i < PF; ++i) zr[i] = zb[3 * i * NTRAJ];

    const float* pz = zb + 3 * PF * NTRAJ;     // next address to prefetch

    float lb0, lb1, lb2;

    #pragma unroll 1
    for (int t = 0; t < TSTEPS; t += PF) {
        #pragma unroll
        for (int u8 = 0; u8 < PF; ++u8) {
            const int t_ = t + u8;
            float z = zr[u8];

            // issue prefetch PF steps ahead (predicated off near the tail)
            float znew = 0.0f;
            if (t_ + PF < TSTEPS) znew = pz[3 * u8 * NTRAJ];
            zr[u8] = znew;

            // ---- predict (dynamics + Jacobian diag-block) ----
            float sp = fmaf(dt, s1, s0);
            float tv = htanh(100.0f * s1);
            float vp = fmaf(-c2, tv, c1 * s1);
            float a  = fmaf(c3, tv * tv, c4);

            float u   = fmaf(dt, p11, p01);
            float n00 = fmaf(dt, u, fmaf(dt, p01, p00)) + q0;
            float n01 = a * u;
            float n11 = fmaf(a * a, p11, q1);

            // ---- update (scalar observation) ----
            float S  = n00 + r;
            float is = __frcp_rn(S);
            float yv = z - sp;
            float K0 = __fmul_rn(n00, is);
            float K1 = __fmul_rn(n01, is);
            s0 = fmaf(K0, yv, sp);
            s1 = fmaf(K1, yv, vp);
            float om = 1.0f - K0;
            p00 = om * n00;
            p01 = om * n01;
            p11 = fmaf(-K1, n01, n11);

            float mah = yv * (is * yv);

            // ---- combine across component lanes (c=0 lanes valid) ----
            float S8  = __shfl_down_sync(0xFFFFFFFFu, S, 8);
            float S16 = __shfl_down_sync(0xFFFFFFFFu, S, 16);
            float m8  = __shfl_down_sync(0xFFFFFFFFu, mah, 8);
            float m16 = __shfl_down_sync(0xFFFFFFFFu, mah, 16);
            float loss = fmaf(S * S8, S16, (mah + m8) + m16);

            const int ph = u8 & 3;
            if (ph == 0) lb0 = loss;
            else if (ph == 1) lb1 = loss;
            else if (ph == 2) lb2 = loss;
            else if (lane < 8) {
                float4 v = make_float4(lb0, lb1, lb2, loss);
                *reinterpret_cast<float4*>(o + (t_ - 3)) = v;
            }
        }
        pz += 3 * PF * NTRAJ;
    }
}

extern "C" void kernel_launch(void* const* d_in, const int* in_sizes, int n_in,
                              void* d_out, int out_size) {
    const float* meas = (const float*)d_in[0];
    const float* init = (const float*)d_in[1];
    const float* dyna = (const float*)d_in[2];
    const float* Q    = (const float*)d_in[3];
    const float* R    = (const float*)d_in[4];
    const float* P0   = (const float*)d_in[5];
    float* out = (float*)d_out;

    dim3 tgrid(KDIM / 32, NTRAJ / 32);
    dim3 tblk(32, 32);
    transpose_k<<<tgrid, tblk>>>(meas);
    ekf_k<<<NTRAJ / 8, 32>>>(init, dyna, Q, R, P0, out);
}